// round 15
// baseline (speedup 1.0000x reference)
#include <cuda_runtime.h>
#include <cuda_fp16.h>
#include <cstdint>

// Shapes (fixed)
#define NB 4
#define NN 512
#define ND 2
#define NH 64
#define NO 2

// ---------------------------------------------------------------------------
__device__ __forceinline__ uint32_t smem_u32(const void* p) {
    uint32_t a;
    asm("{ .reg .u64 t; cvta.to.shared.u64 t, %1; cvt.u32.u64 %0, t; }" : "=r"(a) : "l"(p));
    return a;
}
__device__ __forceinline__ uint32_t pack_f16x2(float a, float b) {
    uint32_t r;
    asm("cvt.rn.f16x2.f32 %0, %2, %1;" : "=r"(r) : "f"(a), "f"(b));
    return r;
}
__device__ __forceinline__ uint32_t h2u(__half2 v) {
    return *reinterpret_cast<uint32_t*>(&v);
}
__device__ __forceinline__ void ldsm_x4(uint32_t& a0, uint32_t& a1, uint32_t& a2,
                                        uint32_t& a3, uint32_t addr) {
    asm volatile("ldmatrix.sync.aligned.m8n8.x4.shared.b16 {%0,%1,%2,%3}, [%4];"
                 : "=r"(a0), "=r"(a1), "=r"(a2), "=r"(a3) : "r"(addr));
}
__device__ __forceinline__ void ldsm_x2(uint32_t& b0, uint32_t& b1, uint32_t addr) {
    asm volatile("ldmatrix.sync.aligned.m8n8.x2.shared.b16 {%0,%1}, [%2];"
                 : "=r"(b0), "=r"(b1) : "r"(addr));
}
__device__ __forceinline__ void mma16816(float& c0, float& c1, float& c2, float& c3,
                                         uint32_t a0, uint32_t a1, uint32_t a2, uint32_t a3,
                                         uint32_t b0, uint32_t b1) {
    asm volatile("mma.sync.aligned.m16n8k16.row.col.f32.f16.f16.f32 "
                 "{%0,%1,%2,%3}, {%4,%5,%6,%7}, {%8,%9}, {%0,%1,%2,%3};"
                 : "+f"(c0), "+f"(c1), "+f"(c2), "+f"(c3)
                 : "r"(a0), "r"(a1), "r"(a2), "r"(a3), "r"(b0), "r"(b1));
}

#define TSTR 72
#define WSTR 72

// ---------------------------------------------------------------------------
// Fully fused: one CTA per node-PAIR, 256 thr, (256,2).
// Edge phase: prologue amortized over 2 nodes, HMMA mainloop, fused epilogue
// -> s into SMEM (su). Head tail: warp-per-node GEMV chain, weight buffers
// aliased onto dead Tsh, output written directly.
// ---------------------------------------------------------------------------
__global__ void __launch_bounds__(256, 2) k_fused(const float* __restrict__ x,
                                                  const float* __restrict__ adj,
                                                  const float* __restrict__ Wn2e,
                                                  const float* __restrict__ bn2e,
                                                  const float* __restrict__ We2e,
                                                  const float* __restrict__ be2e,
                                                  const float* __restrict__ We2n,
                                                  const float* __restrict__ be2n,
                                                  const float* __restrict__ Wn2n,
                                                  const float* __restrict__ bn2n,
                                                  const float* __restrict__ Wo1,
                                                  const float* __restrict__ bo1,
                                                  const float* __restrict__ Wo2,
                                                  const float* __restrict__ bo2,
                                                  float* __restrict__ out) {
    __shared__ __align__(16) __half Tsh[2][128 * TSTR];
    __shared__ __align__(16) char wpool[64 * WSTR * 2];   // Wsh then sx
    __shared__ float su[2][64];        // u per node; later s per node
    __shared__ float sb2[64];
    __shared__ float red[8][32];

    __half* Wsh = (__half*)wpool;
    float* sx = (float*)wpool;         // [512][2] after hoist (stays live)

    int t = threadIdx.x;
    int w = t >> 5;
    int lane = t & 31;
    int bi2 = blockIdx.x;              // 0..1023
    int b = bi2 >> 8;
    int i0 = (bi2 & 255) * 2;
    int mq = w & 3;
    int nq = w >> 2;

    uint32_t Tb0 = smem_u32(Tsh[0]);
    uint32_t Tb1 = smem_u32(Tsh[1]);
    uint32_t Wb = smem_u32(wpool);

    // ---- stage W_e2e [64h][64k] as fp16 ----
    {
        int h = t >> 2;
        int kb = (t & 3) * 16;
        const float* wrow = We2e + h * 64 + kb;
        #pragma unroll
        for (int c = 0; c < 2; ++c) {
            float4 f0 = *(const float4*)(wrow + c * 8);
            float4 f1 = *(const float4*)(wrow + c * 8 + 4);
            uint4 pk;
            pk.x = pack_f16x2(f0.x, f0.y);
            pk.y = pack_f16x2(f0.z, f0.w);
            pk.z = pack_f16x2(f1.x, f1.y);
            pk.w = pack_f16x2(f1.z, f1.w);
            *(uint4*)(Wsh + h * WSTR + kb + c * 8) = pk;
        }
    }
    if (t < 128) {
        int ii = t >> 6;
        int h = t & 63;
        float4 wr = *(const float4*)(Wn2e + h * 4);
        float xi0 = x[(b * NN + i0 + ii) * 2 + 0];
        float xi1 = x[(b * NN + i0 + ii) * 2 + 1];
        su[ii][h] = bn2e[h] + wr.x * xi0 + wr.y * xi1;
    } else if (t < 192) {
        sb2[t - 128] = be2e[t - 128];
    }
    __syncthreads();

    // ---- hoist B fragments ----
    uint32_t Bfr[4][4][2];
    #pragma unroll
    for (int k = 0; k < 4; ++k) {
        #pragma unroll
        for (int nt = 0; nt < 4; ++nt) {
            uint32_t addr = Wb + (uint32_t)(((nq * 32 + nt * 8 + (lane & 7)) * WSTR
                                             + k * 16 + ((lane >> 3) & 1) * 8) * 2);
            ldsm_x2(Bfr[k][nt][0], Bfr[k][nt][1], addr);
        }
    }
    __syncthreads();   // Wsh dead

    // ---- stage x (batch b) ----
    {
        const float* xb = x + b * NN * 2;
        for (int idx = t; idx < NN * 2 / 4; idx += 256)
            ((float4*)sx)[idx] = ((const float4*)xb)[idx];
    }

    int ko = (t & 7) * 8;
    int jrow4 = (t >> 3) * 4;
    __half2 w2h[4], w3h[4];
    #pragma unroll
    for (int c = 0; c < 4; ++c) {
        float4 wr0 = *(const float4*)(Wn2e + (ko + 2 * c) * 4);
        float4 wr1 = *(const float4*)(Wn2e + (ko + 2 * c + 1) * 4);
        w2h[c] = __floats2half2_rn(wr0.z, wr1.z);
        w3h[c] = __floats2half2_rn(wr0.w, wr1.w);
    }
    __syncthreads();   // sx + su visible

    const __half2 z2 = __float2half2_rn(0.f);
    int a_row = lane & 15;
    int a_kh = lane >> 4;
    int rbase = mq * 32 + (lane >> 2);

    for (int ii = 0; ii < 2; ++ii) {
        int i = i0 + ii;

        __half2 uh[4];
        #pragma unroll
        for (int c = 0; c < 4; ++c)
            uh[c] = __floats2half2_rn(su[ii][ko + 2 * c], su[ii][ko + 2 * c + 1]);

        const float* adjrow = adj + i * NN;
        float adjr[4][2][2];
        #pragma unroll
        for (int jt = 0; jt < 4; ++jt) {
            #pragma unroll
            for (int s = 0; s < 2; ++s) {
                adjr[jt][s][0] = adjrow[jt * 128 + rbase + s * 16];
                adjr[jt][s][1] = adjrow[jt * 128 + rbase + s * 16 + 8];
            }
        }

        float sacc[8];
        #pragma unroll
        for (int q = 0; q < 8; ++q) sacc[q] = 0.f;

        // ---- build tile 0 ----
        {
            __half* tb = Tsh[0];
            #pragma unroll
            for (int jj = 0; jj < 4; ++jj) {
                int j = jrow4 + jj;
                __half2 x0h = __float2half2_rn(sx[j * 2 + 0]);
                __half2 x1h = __float2half2_rn(sx[j * 2 + 1]);
                __half2 t0 = __hmax2(__hfma2(w3h[0], x1h, __hfma2(w2h[0], x0h, uh[0])), z2);
                __half2 t1 = __hmax2(__hfma2(w3h[1], x1h, __hfma2(w2h[1], x0h, uh[1])), z2);
                __half2 t2 = __hmax2(__hfma2(w3h[2], x1h, __hfma2(w2h[2], x0h, uh[2])), z2);
                __half2 t3 = __hmax2(__hfma2(w3h[3], x1h, __hfma2(w2h[3], x0h, uh[3])), z2);
                uint4 pk = make_uint4(h2u(t0), h2u(t1), h2u(t2), h2u(t3));
                *(uint4*)(tb + j * TSTR + ko) = pk;
            }
        }
        __syncthreads();

        #pragma unroll
        for (int jt = 0; jt < 4; ++jt) {
            int jbase = jt << 7;
            uint32_t Tcur = (jt & 1) ? Tb1 : Tb0;

            #pragma unroll
            for (int s = 0; s < 2; ++s) {
                float acc[4][4];
                #pragma unroll
                for (int nt = 0; nt < 4; ++nt) {
                    acc[nt][0] = 0.f; acc[nt][1] = 0.f; acc[nt][2] = 0.f; acc[nt][3] = 0.f;
                }
                #pragma unroll
                for (int k = 0; k < 4; ++k) {
                    uint32_t a0, a1, a2, a3;
                    uint32_t a_addr = Tcur + (uint32_t)(((mq * 32 + s * 16 + a_row) * TSTR
                                                        + k * 16 + a_kh * 8) * 2);
                    ldsm_x4(a0, a1, a2, a3, a_addr);
                    #pragma unroll
                    for (int nt = 0; nt < 4; ++nt)
                        mma16816(acc[nt][0], acc[nt][1], acc[nt][2], acc[nt][3],
                                 a0, a1, a2, a3, Bfr[k][nt][0], Bfr[k][nt][1]);
                }
                float aj0 = adjr[jt][s][0];
                float aj1 = adjr[jt][s][1];
                #pragma unroll
                for (int nt = 0; nt < 4; ++nt) {
                    int h0 = nq * 32 + nt * 8 + (lane & 3) * 2;
                    float bb0 = sb2[h0];
                    float bb1 = sb2[h0 + 1];
                    sacc[nt * 2 + 0] += aj0 * fmaxf(acc[nt][0] + bb0, 0.f)
                                      + aj1 * fmaxf(acc[nt][2] + bb0, 0.f);
                    sacc[nt * 2 + 1] += aj0 * fmaxf(acc[nt][1] + bb1, 0.f)
                                      + aj1 * fmaxf(acc[nt][3] + bb1, 0.f);
                }
            }

            if (jt < 3) {
                __half* tb = (jt & 1) ? Tsh[0] : Tsh[1];
                int jb = jbase + 128;
                #pragma unroll
                for (int jj = 0; jj < 4; ++jj) {
                    int j = jrow4 + jj;
                    __half2 x0h = __float2half2_rn(sx[(jb + j) * 2 + 0]);
                    __half2 x1h = __float2half2_rn(sx[(jb + j) * 2 + 1]);
                    __half2 t0 = __hmax2(__hfma2(w3h[0], x1h, __hfma2(w2h[0], x0h, uh[0])), z2);
                    __half2 t1 = __hmax2(__hfma2(w3h[1], x1h, __hfma2(w2h[1], x0h, uh[1])), z2);
                    __half2 t2 = __hmax2(__hfma2(w3h[2], x1h, __hfma2(w2h[2], x0h, uh[2])), z2);
                    __half2 t3 = __hmax2(__hfma2(w3h[3], x1h, __hfma2(w2h[3], x0h, uh[3])), z2);
                    uint4 pk = make_uint4(h2u(t0), h2u(t1), h2u(t2), h2u(t3));
                    *(uint4*)(tb + j * TSTR + ko) = pk;
                }
            }
            __syncthreads();
        }

        // ---- reduce; store s into su[ii] (safe: su[ii] dead after uh) ----
        #pragma unroll
        for (int q = 0; q < 8; ++q) {
            sacc[q] += __shfl_down_sync(0xFFFFFFFFu, sacc[q], 16);
            sacc[q] += __shfl_down_sync(0xFFFFFFFFu, sacc[q], 8);
            sacc[q] += __shfl_down_sync(0xFFFFFFFFu, sacc[q], 4);
        }
        if (lane < 4) {
            #pragma unroll
            for (int nt = 0; nt < 4; ++nt) {
                red[w][nt * 8 + lane * 2 + 0] = sacc[nt * 2 + 0];
                red[w][nt * 8 + lane * 2 + 1] = sacc[nt * 2 + 1];
            }
        }
        __syncthreads();
        if (t < 64) {
            int nq2 = t >> 5;
            int hh = t & 31;
            su[ii][t] = red[nq2 * 4 + 0][hh] + red[nq2 * 4 + 1][hh]
                      + red[nq2 * 4 + 2][hh] + red[nq2 * 4 + 3][hh];
        }
        __syncthreads();
    }

    // ================== fused head tail (warp-per-node, warps 0-1) ==========
    // Weight buffers alias dead Tsh: wA 66*33 f2 (17424B), wB 64*33 f2 (16896B)
    float2* wA = (float2*)Tsh;
    float2* wB = (float2*)((char*)Tsh + 17424);

    // biases + Wo2 into registers early (latency hides under staging barriers)
    float b1a = 0.f, b1b = 0.f, b2a = 0.f, b2b = 0.f, b3a = 0.f, b3b = 0.f;
    float wo2a0 = 0.f, wo2a1 = 0.f, wo2b0 = 0.f, wo2b1 = 0.f, bo2r0 = 0.f, bo2r1 = 0.f;
    if (w < 2) {
        b1a = be2n[lane];  b1b = be2n[32 + lane];
        b2a = bn2n[lane];  b2b = bn2n[32 + lane];
        b3a = bo1[lane];   b3b = bo1[32 + lane];
        wo2a0 = Wo2[lane];        wo2a1 = Wo2[32 + lane];
        wo2b0 = Wo2[64 + lane];   wo2b1 = Wo2[96 + lane];
        bo2r0 = bo2[0];           bo2r1 = bo2[1];
    }

    // stage layer-1 weights
    for (int idx = t; idx < 2048; idx += 256) {
        int k = idx & 63, h = idx >> 6;
        wA[k * 33 + h] = make_float2(We2n[h * 64 + k], We2n[(h + 32) * 64 + k]);
    }
    __syncthreads();

    // prefetch L2 weights; L1 GEMV; STS; barrier
    float2 pf[8];
    #pragma unroll
    for (int c = 0; c < 8; ++c) {
        int idx = t + c * 256;
        int k = idx & 63, h = idx >> 6;
        pf[c] = make_float2(Wn2n[h * 64 + k], Wn2n[(h + 32) * 64 + k]);
    }
    float a0 = b1a, a1 = b1b;
    if (w < 2) {
        #pragma unroll 16
        for (int k = 0; k < 64; ++k) {
            float2 wv = wA[k * 33 + lane];
            float xv = su[w][k];
            a0 = fmaf(wv.x, xv, a0);
            a1 = fmaf(wv.y, xv, a1);
        }
        a0 = fmaxf(a0, 0.f); a1 = fmaxf(a1, 0.f);
        __syncwarp();
        su[w][lane] = a0; su[w][32 + lane] = a1;
    }
    #pragma unroll
    for (int c = 0; c < 8; ++c) {
        int idx = t + c * 256;
        int k = idx & 63, h = idx >> 6;
        wB[k * 33 + h] = pf[c];
    }
    __syncthreads();

    // prefetch Wo1; L2 GEMV; STS; barrier
    float2 pfo[9];
    #pragma unroll
    for (int c = 0; c < 9; ++c) {
        int idx = t + c * 256;
        if (idx < 2112) {
            int cc = idx / 32, h = idx & 31;
            pfo[c] = make_float2(Wo1[h * 66 + cc], Wo1[(h + 32) * 66 + cc]);
        }
    }
    if (w < 2) {
        a0 = b2a; a1 = b2b;
        #pragma unroll 16
        for (int k = 0; k < 64; ++k) {
            float2 wv = wB[k * 33 + lane];
            float xv = su[w][k];
            a0 = fmaf(wv.x, xv, a0);
            a1 = fmaf(wv.y, xv, a1);
        }
        a0 = fmaxf(a0, 0.f); a1 = fmaxf(a1, 0.f);
        __syncwarp();
        su[w][lane] = a0; su[w][32 + lane] = a1;
    }
    #pragma unroll
    for (int c = 0; c < 9; ++c) {
        int idx = t + c * 256;
        if (idx < 2112) {
            int cc = idx / 32, h = idx & 31;
            wA[cc * 33 + h] = pfo[c];
        }
    }
    __syncthreads();

    // L3 + output (warps 0-1 only)
    if (w < 2) {
        int i = i0 + w;
        a0 = b3a; a1 = b3b;
        {
            float x0 = sx[i * 2 + 0], x1 = sx[i * 2 + 1];
            float2 wv0 = wA[0 * 33 + lane];
            float2 wv1 = wA[1 * 33 + lane];
            a0 = fmaf(wv0.x, x0, fmaf(wv1.x, x1, a0));
            a1 = fmaf(wv0.y, x0, fmaf(wv1.y, x1, a1));
        }
        #pragma unroll 16
        for (int k = 0; k < 64; ++k) {
            float2 wv = wA[(k + 2) * 33 + lane];
            float xv = su[w][k];
            a0 = fmaf(wv.x, xv, a0);
            a1 = fmaf(wv.y, xv, a1);
        }
        a0 = fmaxf(a0, 0.f); a1 = fmaxf(a1, 0.f);

        float p0 = wo2a0 * a0 + wo2a1 * a1;
        float p1 = wo2b0 * a0 + wo2b1 * a1;
        #pragma unroll
        for (int ofs = 16; ofs > 0; ofs >>= 1) {
            p0 += __shfl_down_sync(0xFFFFFFFFu, p0, ofs);
            p1 += __shfl_down_sync(0xFFFFFFFFu, p1, ofs);
        }
        if (lane == 0) {
            out[(b * NN + i) * 2 + 0] = bo2r0 + p0;
            out[(b * NN + i) * 2 + 1] = bo2r1 + p1;
        }
    }
}

// ---------------------------------------------------------------------------
extern "C" void kernel_launch(void* const* d_in, const int* in_sizes, int n_in,
                              void* d_out, int out_size) {
    const float* input = (const float*)d_in[0];
    const float* adj   = (const float*)d_in[1];
    const float* W_n2e = (const float*)d_in[2];
    const float* b_n2e = (const float*)d_in[3];
    const float* W_e2e = (const float*)d_in[4];
    const float* b_e2e = (const float*)d_in[5];
    const float* W_e2n = (const float*)d_in[6];
    const float* b_e2n = (const float*)d_in[7];
    const float* W_n2n = (const float*)d_in[8];
    const float* b_n2n = (const float*)d_in[9];
    const float* W_o1  = (const float*)d_in[10];
    const float* b_o1  = (const float*)d_in[11];
    const float* W_o2  = (const float*)d_in[12];
    const float* b_o2  = (const float*)d_in[13];
    float* out = (float*)d_out;

    k_fused<<<NB * NN / 2, 256>>>(input, adj, W_n2e, b_n2e, W_e2e, b_e2e,
                                  W_e2n, b_e2n, W_n2n, b_n2n,
                                  W_o1, b_o1, W_o2, b_o2, out);
}

// round 16
// speedup vs baseline: 1.0640x; 1.0640x over previous
#include <cuda_runtime.h>
#include <cuda_fp16.h>
#include <cstdint>

// Shapes (fixed)
#define NB 4
#define NN 512
#define ND 2
#define NH 64
#define NO 2

// Scratch
__device__ float g_s[NB * NN * NH];

// ---------------------------------------------------------------------------
__device__ __forceinline__ uint32_t smem_u32(const void* p) {
    uint32_t a;
    asm("{ .reg .u64 t; cvta.to.shared.u64 t, %1; cvt.u32.u64 %0, t; }" : "=r"(a) : "l"(p));
    return a;
}
__device__ __forceinline__ uint32_t pack_f16x2(float a, float b) {
    uint32_t r;
    asm("cvt.rn.f16x2.f32 %0, %2, %1;" : "=r"(r) : "f"(a), "f"(b));
    return r;
}
__device__ __forceinline__ uint32_t h2u(__half2 v) {
    return *reinterpret_cast<uint32_t*>(&v);
}
__device__ __forceinline__ void ldsm_x2(uint32_t& b0, uint32_t& b1, uint32_t addr) {
    asm volatile("ldmatrix.sync.aligned.m8n8.x2.shared.b16 {%0,%1}, [%2];"
                 : "=r"(b0), "=r"(b1) : "r"(addr));
}
__device__ __forceinline__ void mma16816(float& c0, float& c1, float& c2, float& c3,
                                         uint32_t a0, uint32_t a1, uint32_t a2, uint32_t a3,
                                         uint32_t b0, uint32_t b1) {
    asm volatile("mma.sync.aligned.m16n8k16.row.col.f32.f16.f16.f32 "
                 "{%0,%1,%2,%3}, {%4,%5,%6,%7}, {%8,%9}, {%0,%1,%2,%3};"
                 : "+f"(c0), "+f"(c1), "+f"(c2), "+f"(c3)
                 : "r"(a0), "r"(a1), "r"(a2), "r"(a3), "r"(b0), "r"(b1));
}

#define WSTR 72

// ---------------------------------------------------------------------------
// Edge kernel: one CTA per node-PAIR, 256 thr, (256,2).
// A fragments computed DIRECTLY IN REGISTERS (no T tile, no mainloop barriers,
// no A-ldmatrix). B fragments hoisted once. Fused relu(+b2)*adj epilogue.
// ---------------------------------------------------------------------------
__global__ void __launch_bounds__(256, 2) k_edge_mma(const float* __restrict__ x,
                                                     const float* __restrict__ adj,
                                                     const float* __restrict__ Wn2e,
                                                     const float* __restrict__ bn2e,
                                                     const float* __restrict__ We2e,
                                                     const float* __restrict__ be2e) {
    __shared__ __align__(16) char wpool[64 * WSTR * 2];   // Wsh, then sx
    __shared__ float su[2][64];
    __shared__ float red[8][32];

    __half* Wsh = (__half*)wpool;
    float2* sx2 = (float2*)wpool;      // [512] float2 after hoist

    int t = threadIdx.x;
    int w = t >> 5;
    int lane = t & 31;
    int bi2 = blockIdx.x;              // 0..1023
    int b = bi2 >> 8;
    int i0 = (bi2 & 255) * 2;
    int mq = w & 3;                    // m-block: j rows [32mq, 32mq+32)
    int nq = w >> 2;                   // n-block: h cols [32nq, 32nq+32)

    uint32_t Wb = smem_u32(wpool);

    // ---- stage W_e2e [64h][64k] as fp16 (for B-fragment hoist) ----
    {
        int h = t >> 2;
        int kb = (t & 3) * 16;
        const float* wrow = We2e + h * 64 + kb;
        #pragma unroll
        for (int c = 0; c < 2; ++c) {
            float4 f0 = *(const float4*)(wrow + c * 8);
            float4 f1 = *(const float4*)(wrow + c * 8 + 4);
            uint4 pk;
            pk.x = pack_f16x2(f0.x, f0.y);
            pk.y = pack_f16x2(f0.z, f0.w);
            pk.z = pack_f16x2(f1.x, f1.y);
            pk.w = pack_f16x2(f1.z, f1.w);
            *(uint4*)(Wsh + h * WSTR + kb + c * 8) = pk;
        }
    }
    // u for both nodes
    if (t < 128) {
        int ii = t >> 6;
        int h = t & 63;
        float4 wr = *(const float4*)(Wn2e + h * 4);
        float xi0 = x[(b * NN + i0 + ii) * 2 + 0];
        float xi1 = x[(b * NN + i0 + ii) * 2 + 1];
        su[ii][h] = bn2e[h] + wr.x * xi0 + wr.y * xi1;
    }
    __syncthreads();

    // ---- hoist B fragments (16 ldmatrix total per warp) ----
    uint32_t Bfr[4][4][2];
    #pragma unroll
    for (int k = 0; k < 4; ++k) {
        #pragma unroll
        for (int nt = 0; nt < 4; ++nt) {
            uint32_t addr = Wb + (uint32_t)(((nq * 32 + nt * 8 + (lane & 7)) * WSTR
                                             + k * 16 + ((lane >> 3) & 1) * 8) * 2);
            ldsm_x2(Bfr[k][nt][0], Bfr[k][nt][1], addr);
        }
    }
    __syncthreads();   // Wsh dead

    // ---- stage x (batch b) over Wsh ----
    {
        const float* xb = x + b * NN * 2;
        for (int idx = t; idx < NN * 2 / 4; idx += 256)
            ((float4*)sx2)[idx] = ((const float4*)xb)[idx];
    }

    // ---- per-thread k constants: klo = (lane&3)*2; k0 = kc*16 + kh*8 + klo ----
    int klo = (lane & 3) * 2;
    __half2 w2p[4][2], w3p[4][2];
    #pragma unroll
    for (int kc = 0; kc < 4; ++kc) {
        #pragma unroll
        for (int kh = 0; kh < 2; ++kh) {
            int k0 = kc * 16 + kh * 8 + klo;
            float4 wr0 = *(const float4*)(Wn2e + k0 * 4);
            float4 wr1 = *(const float4*)(Wn2e + (k0 + 1) * 4);
            w2p[kc][kh] = __floats2half2_rn(wr0.z, wr1.z);
            w3p[kc][kh] = __floats2half2_rn(wr0.w, wr1.w);
        }
    }
    // sb2 values this thread needs (h0 = nq*32 + nt*8 + klo)
    float sb2r[4][2];
    #pragma unroll
    for (int nt = 0; nt < 4; ++nt) {
        sb2r[nt][0] = be2e[nq * 32 + nt * 8 + klo];
        sb2r[nt][1] = be2e[nq * 32 + nt * 8 + klo + 1];
    }
    __syncthreads();   // sx staged, su visible

    const __half2 z2 = __float2half2_rn(0.f);
    int r0 = lane >> 2;
    int rbase = mq * 32 + r0;

    for (int ii = 0; ii < 2; ++ii) {
        int i = i0 + ii;

        // u at this thread's k positions
        __half2 up[4][2];
        #pragma unroll
        for (int kc = 0; kc < 4; ++kc) {
            #pragma unroll
            for (int kh = 0; kh < 2; ++kh) {
                int k0 = kc * 16 + kh * 8 + klo;
                up[kc][kh] = __floats2half2_rn(su[ii][k0], su[ii][k0 + 1]);
            }
        }

        // adj preload (16 regs)
        const float* adjrow = adj + i * NN;
        float adjr[4][2][2];
        #pragma unroll
        for (int jt = 0; jt < 4; ++jt) {
            #pragma unroll
            for (int s = 0; s < 2; ++s) {
                adjr[jt][s][0] = adjrow[jt * 128 + rbase + s * 16];
                adjr[jt][s][1] = adjrow[jt * 128 + rbase + s * 16 + 8];
            }
        }

        float sacc[8];
        #pragma unroll
        for (int q = 0; q < 8; ++q) sacc[q] = 0.f;

        #pragma unroll
        for (int jt = 0; jt < 4; ++jt) {
            int jbase = jt << 7;

            #pragma unroll
            for (int s = 0; s < 2; ++s) {
                // x for this thread's two j rows
                int j0 = jbase + mq * 32 + s * 16 + r0;
                float2 xa = sx2[j0];
                float2 xb = sx2[j0 + 8];
                __half2 xa0 = __float2half2_rn(xa.x);
                __half2 xa1 = __float2half2_rn(xa.y);
                __half2 xb0 = __float2half2_rn(xb.x);
                __half2 xb1 = __float2half2_rn(xb.y);

                float acc[4][4];
                #pragma unroll
                for (int nt = 0; nt < 4; ++nt) {
                    acc[nt][0] = 0.f; acc[nt][1] = 0.f; acc[nt][2] = 0.f; acc[nt][3] = 0.f;
                }

                #pragma unroll
                for (int kc = 0; kc < 4; ++kc) {
                    // A fragments in registers: a0,a1 = kh0 rows j0,j0+8; a2,a3 = kh1
                    __half2 a0 = __hmax2(__hfma2(w3p[kc][0], xa1,
                                    __hfma2(w2p[kc][0], xa0, up[kc][0])), z2);
                    __half2 a1 = __hmax2(__hfma2(w3p[kc][0], xb1,
                                    __hfma2(w2p[kc][0], xb0, up[kc][0])), z2);
                    __half2 a2 = __hmax2(__hfma2(w3p[kc][1], xa1,
                                    __hfma2(w2p[kc][1], xa0, up[kc][1])), z2);
                    __half2 a3 = __hmax2(__hfma2(w3p[kc][1], xb1,
                                    __hfma2(w2p[kc][1], xb0, up[kc][1])), z2);
                    uint32_t ua0 = h2u(a0), ua1 = h2u(a1), ua2 = h2u(a2), ua3 = h2u(a3);
                    #pragma unroll
                    for (int nt = 0; nt < 4; ++nt)
                        mma16816(acc[nt][0], acc[nt][1], acc[nt][2], acc[nt][3],
                                 ua0, ua1, ua2, ua3, Bfr[kc][nt][0], Bfr[kc][nt][1]);
                }

                float aj0 = adjr[jt][s][0];
                float aj1 = adjr[jt][s][1];
                #pragma unroll
                for (int nt = 0; nt < 4; ++nt) {
                    float bb0 = sb2r[nt][0];
                    float bb1 = sb2r[nt][1];
                    sacc[nt * 2 + 0] += aj0 * fmaxf(acc[nt][0] + bb0, 0.f)
                                      + aj1 * fmaxf(acc[nt][2] + bb0, 0.f);
                    sacc[nt * 2 + 1] += aj0 * fmaxf(acc[nt][1] + bb1, 0.f)
                                      + aj1 * fmaxf(acc[nt][3] + bb1, 0.f);
                }
            }
        }

        // ---- reduce and store s ----
        #pragma unroll
        for (int q = 0; q < 8; ++q) {
            sacc[q] += __shfl_down_sync(0xFFFFFFFFu, sacc[q], 16);
            sacc[q] += __shfl_down_sync(0xFFFFFFFFu, sacc[q], 8);
            sacc[q] += __shfl_down_sync(0xFFFFFFFFu, sacc[q], 4);
        }
        if (lane < 4) {
            #pragma unroll
            for (int nt = 0; nt < 4; ++nt) {
                red[w][nt * 8 + lane * 2 + 0] = sacc[nt * 2 + 0];
                red[w][nt * 8 + lane * 2 + 1] = sacc[nt * 2 + 1];
            }
        }
        __syncthreads();
        if (t < 64) {
            int nq2 = t >> 5;
            int hh = t & 31;
            g_s[(b * NN + i) * 64 + t] = red[nq2 * 4 + 0][hh] + red[nq2 * 4 + 1][hh]
                                       + red[nq2 * 4 + 2][hh] + red[nq2 * 4 + 3][hh];
        }
        __syncthreads();
    }
}

// ---------------------------------------------------------------------------
// Head kernel (R11-measured version, 15.0 us)
// ---------------------------------------------------------------------------
__global__ void __launch_bounds__(256) k_head(const float* __restrict__ x,
                                              const float* __restrict__ We2n,
                                              const float* __restrict__ be2n,
                                              const float* __restrict__ Wn2n,
                                              const float* __restrict__ bn2n,
                                              const float* __restrict__ Wo1,
                                              const float* __restrict__ bo1,
                                              const float* __restrict__ Wo2,
                                              const float* __restrict__ bo2,
                                              float* __restrict__ out) {
    __shared__ float2 wA[66 * 33];
    __shared__ float2 wB[64 * 33];
    __shared__ float sio[8][64];
    __shared__ float sb[3][64];
    __shared__ float swo2[128];
    __shared__ float sb2o[2];
    __shared__ float sxn[8][2];

    int t = threadIdx.x;
    int w = t >> 5;
    int lane = t & 31;
    int nbase = blockIdx.x * 8;

    for (int idx = t; idx < 2048; idx += 256) {
        int k = idx & 63, h = idx >> 6;
        wA[k * 33 + h] = make_float2(We2n[h * 64 + k], We2n[(h + 32) * 64 + k]);
    }
    {
        int idx = t;
        sio[idx >> 6][idx & 63] = g_s[(nbase + (idx >> 6)) * 64 + (idx & 63)];
        idx = t + 256;
        sio[idx >> 6][idx & 63] = g_s[(nbase + (idx >> 6)) * 64 + (idx & 63)];
    }
    if (t < 64) { sb[0][t] = be2n[t]; sb[1][t] = bn2n[t]; sb[2][t] = bo1[t]; }
    if (t < 128) swo2[t] = Wo2[t];
    if (t < 2) sb2o[t] = bo2[t];
    if (t < 16) sxn[t >> 1][t & 1] = x[(nbase + (t >> 1)) * 2 + (t & 1)];
    __syncthreads();

    float2 pf[8];
    #pragma unroll
    for (int c = 0; c < 8; ++c) {
        int idx = t + c * 256;
        int k = idx & 63, h = idx >> 6;
        pf[c] = make_float2(Wn2n[h * 64 + k], Wn2n[(h + 32) * 64 + k]);
    }
    float a0 = sb[0][lane], a1 = sb[0][32 + lane];
    #pragma unroll 16
    for (int k = 0; k < 64; ++k) {
        float2 wv = wA[k * 33 + lane];
        float xv = sio[w][k];
        a0 = fmaf(wv.x, xv, a0);
        a1 = fmaf(wv.y, xv, a1);
    }
    a0 = fmaxf(a0, 0.f); a1 = fmaxf(a1, 0.f);
    __syncwarp();
    sio[w][lane] = a0; sio[w][32 + lane] = a1;
    #pragma unroll
    for (int c = 0; c < 8; ++c) {
        int idx = t + c * 256;
        int k = idx & 63, h = idx >> 6;
        wB[k * 33 + h] = pf[c];
    }
    __syncthreads();

    float2 pfo[9];
    #pragma unroll
    for (int c = 0; c < 9; ++c) {
        int idx = t + c * 256;
        if (idx < 2112) {
            int cc = idx / 32, h = idx & 31;
            pfo[c] = make_float2(Wo1[h * 66 + cc], Wo1[(h + 32) * 66 + cc]);
        }
    }
    a0 = sb[1][lane]; a1 = sb[1][32 + lane];
    #pragma unroll 16
    for (int k = 0; k < 64; ++k) {
        float2 wv = wB[k * 33 + lane];
        float xv = sio[w][k];
        a0 = fmaf(wv.x, xv, a0);
        a1 = fmaf(wv.y, xv, a1);
    }
    a0 = fmaxf(a0, 0.f); a1 = fmaxf(a1, 0.f);
    __syncwarp();
    sio[w][lane] = a0; sio[w][32 + lane] = a1;
    #pragma unroll
    for (int c = 0; c < 9; ++c) {
        int idx = t + c * 256;
        if (idx < 2112) {
            int cc = idx / 32, h = idx & 31;
            wA[cc * 33 + h] = pfo[c];
        }
    }
    __syncthreads();

    a0 = sb[2][lane]; a1 = sb[2][32 + lane];
    {
        float x0 = sxn[w][0], x1 = sxn[w][1];
        float2 wv0 = wA[0 * 33 + lane];
        float2 wv1 = wA[1 * 33 + lane];
        a0 = fmaf(wv0.x, x0, fmaf(wv1.x, x1, a0));
        a1 = fmaf(wv0.y, x0, fmaf(wv1.y, x1, a1));
    }
    #pragma unroll 16
    for (int k = 0; k < 64; ++k) {
        float2 wv = wA[(k + 2) * 33 + lane];
        float xv = sio[w][k];
        a0 = fmaf(wv.x, xv, a0);
        a1 = fmaf(wv.y, xv, a1);
    }
    a0 = fmaxf(a0, 0.f); a1 = fmaxf(a1, 0.f);

    #pragma unroll
    for (int o = 0; o < 2; ++o) {
        float p = swo2[o * 64 + lane] * a0 + swo2[o * 64 + 32 + lane] * a1;
        p += __shfl_down_sync(0xFFFFFFFFu, p, 16);
        p += __shfl_down_sync(0xFFFFFFFFu, p, 8);
        p += __shfl_down_sync(0xFFFFFFFFu, p, 4);
        p += __shfl_down_sync(0xFFFFFFFFu, p, 2);
        p += __shfl_down_sync(0xFFFFFFFFu, p, 1);
        if (lane == 0) out[(nbase + w) * 2 + o] = sb2o[o] + p;
    }
}

// ---------------------------------------------------------------------------
extern "C" void kernel_launch(void* const* d_in, const int* in_sizes, int n_in,
                              void* d_out, int out_size) {
    const float* input = (const float*)d_in[0];
    const float* adj   = (const float*)d_in[1];
    const float* W_n2e = (const float*)d_in[2];
    const float* b_n2e = (const float*)d_in[3];
    const float* W_e2e = (const float*)d_in[4];
    const float* b_e2e = (const float*)d_in[5];
    const float* W_e2n = (const float*)d_in[6];
    const float* b_e2n = (const float*)d_in[7];
    const float* W_n2n = (const float*)d_in[8];
    const float* b_n2n = (const float*)d_in[9];
    const float* W_o1  = (const float*)d_in[10];
    const float* b_o1  = (const float*)d_in[11];
    const float* W_o2  = (const float*)d_in[12];
    const float* b_o2  = (const float*)d_in[13];
    float* out = (float*)d_out;

    k_edge_mma<<<NB * NN / 2, 256>>>(input, adj, W_n2e, b_n2e, W_e2e, b_e2e);
    k_head<<<NB * NN / 8, 256>>>(input, W_e2n, b_e2n, W_n2n, b_n2n,
                                 W_o1, b_o1, W_o2, b_o2, out);
}